// round 16
// baseline (speedup 1.0000x reference)
#include <cuda_runtime.h>
#include <cuda_fp16.h>
#include <cstdint>

// ---------------------------------------------------------------------------
// Poly2d via warp-level HMMA (mma.sync m16n8k16, fp16 in / fp32 acc).
// 54 features/channel; K packed 2x56=112 per channel pair (7 k-steps),
// 240B-stride rows (no swizzle). Round 16: bias computation moved INTO the
// main kernel (hidden behind the mainloop; one MLP-batched DRAM round trip)
// so prep has no serial tail. Mainloop = exact R11 (best passing).
// 256 CTAs x 128 threads (2x2 warp grid), 2 CTAs/SM.
// ---------------------------------------------------------------------------

#define NCH   64
#define NOUT  64
#define KPAIR 112
#define ROWB  240
#define NPAIR 32

__device__ __align__(16) unsigned short g_Wp[NPAIR * NOUT * KPAIR];

// dynamic smem layout (bytes)
#define A_BUF  (64 * ROWB)                   // 15360
#define B_BUF  (NOUT * ROWB)                 // 15360
#define OFF_A  0                             // 2 x A_BUF = 30720
#define OFF_B  (2 * A_BUF)                   // 2 x B_BUF = 30720
#define OFF_X  (OFF_B + 2 * B_BUF)           // 2 x 408 floats = 3264
#define OFF_BS (OFF_X + 3264)                // 2 x 64 floats bias partials
#define SMEM_SZ (OFF_BS + 512 + 64)

__device__ __forceinline__ uint32_t s2u(const void* p) {
    return (uint32_t)__cvta_generic_to_shared(p);
}
__device__ __forceinline__ void cpa4(uint32_t s, const void* g, bool ok) {
    asm volatile("cp.async.ca.shared.global [%0], [%1], 4, %2;\n"
                 :: "r"(s), "l"(g), "r"(ok ? 4 : 0));
}
__device__ __forceinline__ void cpa16(uint32_t s, const void* g) {
    asm volatile("cp.async.cg.shared.global [%0], [%1], 16;\n"
                 :: "r"(s), "l"(g));
}
__device__ __forceinline__ void ldsm4(uint32_t& r0, uint32_t& r1, uint32_t& r2,
                                      uint32_t& r3, uint32_t addr) {
    asm volatile("ldmatrix.sync.aligned.m8n8.x4.shared.b16 {%0,%1,%2,%3}, [%4];"
                 : "=r"(r0), "=r"(r1), "=r"(r2), "=r"(r3) : "r"(addr));
}
__device__ __forceinline__ void mma16816(float& c0, float& c1, float& c2, float& c3,
                                         uint32_t a0, uint32_t a1, uint32_t a2,
                                         uint32_t a3, uint32_t b0, uint32_t b1) {
    asm volatile(
        "mma.sync.aligned.m16n8k16.row.col.f32.f16.f16.f32 "
        "{%0,%1,%2,%3}, {%4,%5,%6,%7}, {%8,%9}, {%0,%1,%2,%3};"
        : "+f"(c0), "+f"(c1), "+f"(c2), "+f"(c3)
        : "r"(a0), "r"(a1), "r"(a2), "r"(a3), "r"(b0), "r"(b1));
}

// ---------------------------------------------------------------------------
// Prep: 64 CTAs, one channel c each; writes halves [p*56, p*56+56) (p=c&1)
// of every o-row in pair block c>>1. No bias work -> no serial tail.
// ---------------------------------------------------------------------------
__global__ void __launch_bounds__(256)
poly_prep(const float* __restrict__ filters) {
    __shared__ float fsm[NOUT * 100];                        // 25.6KB
    __shared__ __align__(16) unsigned short wsm[NOUT * 56];  // 7KB
    const int c = blockIdx.x, tid = threadIdx.x;
    const int pj = c >> 1, p = c & 1;
    const int o = tid & 63, q = tid >> 6;

    for (int i = tid; i < NOUT * 100; i += 256)
        fsm[i] = filters[(i / 100) * 6400 + c * 100 + (i % 100)];
    __syncthreads();

    {
        const float* F = fsm + o * 100;
        for (int k = 14 * q; k < 14 * q + 14; ++k) {
            float v;
            if (k < 9) {
                const int t = k + 1;
                v = F[t] + F[t * 10];
            } else if (k < 54) {
                int idx = k - 9, a = 0;
                while (idx >= 9 - a) { idx -= 9 - a; ++a; }
                const int i1 = a + 1, j1 = a + idx + 1;
                v = (i1 == j1) ? F[i1 * 10 + i1]
                               : (F[i1 * 10 + j1] + F[j1 * 10 + i1]);
            } else {
                v = 0.0f;
            }
            wsm[o * 56 + k] = __half_as_ushort(__float2half_rn(v));
        }
    }
    __syncthreads();

    const uint4* srcp = (const uint4*)wsm;
    for (int i = tid; i < 448; i += 256) {
        const int oo = i / 7, qq = i % 7;
        *(uint4*)(g_Wp + pj * NOUT * KPAIR + oo * KPAIR + p * 56 + qq * 8) =
            srcp[i];
    }
}

// ---------------------------------------------------------------------------
// Main kernel: 256 CTAs (b, row) x 128 threads (4 warps), 2x2 warp grid over
// D[64 px, 64 o]; iter = channel pair, K=112 (7 k-steps). Bias partials
// computed at start (overlapped with stage(0) DRAM round trip).
// ---------------------------------------------------------------------------
extern __shared__ unsigned char smdyn[];

__global__ void __launch_bounds__(128, 2)
poly_mma(const float* __restrict__ x, float* __restrict__ out,
         const float* __restrict__ filters, const float* __restrict__ biases) {
    const uint32_t smb = s2u(smdyn);
    const int tid = threadIdx.x, lane = tid & 31, wid = tid >> 5;
    const int m = tid & 63, h = tid >> 6;           // pixel col, pair-channel
    const int mrow = wid >> 1, ncol = wid & 1;      // 2x2 warp grid
    const int b = blockIdx.x >> 6;
    const int r = blockIdx.x & 63;

    float acc[2][4][4];
    #pragma unroll
    for (int mt = 0; mt < 2; ++mt)
        #pragma unroll
        for (int n8 = 0; n8 < 4; ++n8)
            #pragma unroll
            for (int q = 0; q < 4; ++q) acc[mt][n8][q] = 0.0f;

    // stage channel pair j into buffer j&1
    auto stage = [&](int j) {
        const uint32_t buf = (uint32_t)(j & 1);
        #pragma unroll
        for (int i = tid; i < 408; i += 128) {      // 2 ch x 3 rows x 68 cols
            const int p = i / 204, rem = i % 204;
            const int rr = rem / 68, col = rem % 68;
            const int gr = r - 1 + rr, gw = col - 1;
            const bool ok = ((unsigned)gr < 64u) && ((unsigned)gw < 64u);
            const int c = 2 * j + p;
            const float* src =
                x + (((b * NCH + c) * 64 + (ok ? gr : 0)) * 64 + (ok ? gw : 0));
            cpa4(smb + OFF_X + (buf * 408 + (uint32_t)i) * 4, src, ok);
        }
        const uint4* srcw = (const uint4*)(g_Wp + j * NOUT * KPAIR);
        #pragma unroll
        for (int i = tid; i < 896; i += 128) {      // 64 rows x 14 x 16B
            const int row = i / 14, col = i % 14;
            cpa16(smb + OFF_B + buf * B_BUF + (uint32_t)(row * ROWB + col * 16),
                  srcw + i);
        }
    };

    stage(0);
    asm volatile("cp.async.commit_group;" ::: "memory");

    // ---- bias partials: 32 independent LDGs/thread, one MLP round trip,
    // overlaps with stage(0)'s cp.async round trip ----
    {
        float s0 = 0.f, s1 = 0.f, s2 = 0.f, s3 = 0.f;
        const float* fp = filters + m * 6400 + (h * 32) * 100;
        #pragma unroll
        for (int cc = 0; cc < 32; cc += 4) {
            s0 += fp[(cc)     * 100];
            s1 += fp[(cc + 1) * 100];
            s2 += fp[(cc + 2) * 100];
            s3 += fp[(cc + 3) * 100];
        }
        float bs = (s0 + s1) + (s2 + s3);
        if (h == 0) bs += biases[m];
        ((float*)(smdyn + OFF_BS))[h * 64 + m] = bs;
    }

    // ldmatrix lane base offsets (no swizzle; k-step adds ks*32 bytes)
    uint32_t a_off[2], b_off[2];
    #pragma unroll
    for (int mt = 0; mt < 2; ++mt)
        a_off[mt] = (uint32_t)((mrow * 32 + mt * 16 + (lane & 15)) * ROWB +
                               (lane >> 4) * 16);
    #pragma unroll
    for (int nt = 0; nt < 2; ++nt)
        b_off[nt] = (uint32_t)((ncol * 32 + nt * 16 + (lane & 15)) * ROWB +
                               (lane >> 4) * 16);

    for (int j = 0; j < NPAIR; ++j) {
        asm volatile("cp.async.wait_group 0;" ::: "memory");
        __syncthreads();   // x[j], B[j] ready; A[j&1] free (MMA j-2 done)

        if (j + 1 < NPAIR) stage(j + 1);
        asm volatile("cp.async.commit_group;" ::: "memory");

        const uint32_t abuf = smb + OFF_A + (uint32_t)(j & 1) * A_BUF;
        const uint32_t bbuf = smb + OFF_B + (uint32_t)(j & 1) * B_BUF;

        // ---- featgen: this thread's channel (h) of the pair ----
        {
            const float* xbp =
                (const float*)(smdyn + OFF_X) + (j & 1) * 408 + h * 204;
            float t[9];
            #pragma unroll
            for (int rr = 0; rr < 3; ++rr)
                #pragma unroll
                for (int dx = 0; dx < 3; ++dx)
                    t[rr * 3 + dx] = xbp[rr * 68 + m + dx];

            float fl[54];
            #pragma unroll
            for (int tt = 0; tt < 9; ++tt) fl[tt] = t[tt];
            {
                int k = 9;
                #pragma unroll
                for (int i = 0; i < 9; ++i)
                    #pragma unroll
                    for (int jj = i; jj < 9; ++jj) fl[k++] = t[i] * t[jj];
            }

            uint32_t hr[28];
            #pragma unroll
            for (int u = 0; u < 27; ++u) {
                __half2 hh = __floats2half2_rn(fl[2 * u], fl[2 * u + 1]);
                hr[u] = *reinterpret_cast<uint32_t*>(&hh);
            }
            hr[27] = 0u;   // pad halves 54,55

            const uint32_t dst0 = abuf + (uint32_t)(m * ROWB + h * 112);
            #pragma unroll
            for (int q = 0; q < 7; ++q)
                asm volatile("st.shared.v4.b32 [%0], {%1,%2,%3,%4};"
                             :: "r"(dst0 + (uint32_t)q * 16),
                                "r"(hr[4 * q]), "r"(hr[4 * q + 1]),
                                "r"(hr[4 * q + 2]), "r"(hr[4 * q + 3])
                             : "memory");
        }
        __syncthreads();   // A pair ready (also orders bias partial stores)

        // ---- HMMA over K = 112 (7 k-steps) ----
        #pragma unroll
        for (int ks = 0; ks < 7; ++ks) {
            const uint32_t kl = (uint32_t)ks * 32;
            uint32_t a0[4], a1[4], bA[4], bB[4];
            ldsm4(a0[0], a0[1], a0[2], a0[3], abuf + a_off[0] + kl);
            ldsm4(a1[0], a1[1], a1[2], a1[3], abuf + a_off[1] + kl);
            ldsm4(bA[0], bA[1], bA[2], bA[3], bbuf + b_off[0] + kl);
            ldsm4(bB[0], bB[1], bB[2], bB[3], bbuf + b_off[1] + kl);

            mma16816(acc[0][0][0], acc[0][0][1], acc[0][0][2], acc[0][0][3],
                     a0[0], a0[1], a0[2], a0[3], bA[0], bA[2]);
            mma16816(acc[0][1][0], acc[0][1][1], acc[0][1][2], acc[0][1][3],
                     a0[0], a0[1], a0[2], a0[3], bA[1], bA[3]);
            mma16816(acc[0][2][0], acc[0][2][1], acc[0][2][2], acc[0][2][3],
                     a0[0], a0[1], a0[2], a0[3], bB[0], bB[2]);
            mma16816(acc[0][3][0], acc[0][3][1], acc[0][3][2], acc[0][3][3],
                     a0[0], a0[1], a0[2], a0[3], bB[1], bB[3]);
            mma16816(acc[1][0][0], acc[1][0][1], acc[1][0][2], acc[1][0][3],
                     a1[0], a1[1], a1[2], a1[3], bA[0], bA[2]);
            mma16816(acc[1][1][0], acc[1][1][1], acc[1][1][2], acc[1][1][3],
                     a1[0], a1[1], a1[2], a1[3], bA[1], bA[3]);
            mma16816(acc[1][2][0], acc[1][2][1], acc[1][2][2], acc[1][2][3],
                     a1[0], a1[1], a1[2], a1[3], bB[0], bB[2]);
            mma16816(acc[1][3][0], acc[1][3][1], acc[1][3][2], acc[1][3][3],
                     a1[0], a1[1], a1[2], a1[3], bB[1], bB[3]);
        }
    }

    // ---- epilogue: c-frag -> global, + bias (from smem partials) ----
    const float* bsm = (const float*)(smdyn + OFF_BS);
    const int obase = ncol * 32 + (lane & 3) * 2;
    float2 bias2v[4];
    #pragma unroll
    for (int n8 = 0; n8 < 4; ++n8) {
        const int o = obase + n8 * 8;
        bias2v[n8].x = bsm[o]     + bsm[64 + o];
        bias2v[n8].y = bsm[o + 1] + bsm[64 + o + 1];
    }

    #pragma unroll
    for (int mt = 0; mt < 2; ++mt) {
        #pragma unroll
        for (int half = 0; half < 2; ++half) {
            const int cc = mrow * 32 + mt * 16 + (lane >> 2) + half * 8;
            float* op = out + ((b * NOUT) * 64 + r) * 64 + cc;
            #pragma unroll
            for (int n8 = 0; n8 < 4; ++n8) {
                const int o = obase + n8 * 8;
                op[(o)     * 4096] = acc[mt][n8][half * 2]     + bias2v[n8].x;
                op[(o + 1) * 4096] = acc[mt][n8][half * 2 + 1] + bias2v[n8].y;
            }
        }
    }
}

// ---------------------------------------------------------------------------
extern "C" void kernel_launch(void* const* d_in, const int* in_sizes, int n_in,
                              void* d_out, int out_size) {
    const float* x       = (const float*)d_in[0];  // [4,64,64,64]
    const float* filters = (const float*)d_in[1];  // [64,64,10,10]
    const float* biases  = (const float*)d_in[2];  // [64,1]
    float* out = (float*)d_out;                    // [4,64,64,64]
    (void)in_sizes; (void)n_in; (void)out_size;

    static int attr_set = 0;
    if (!attr_set) {
        cudaFuncSetAttribute(poly_mma,
                             cudaFuncAttributeMaxDynamicSharedMemorySize,
                             SMEM_SZ);
        attr_set = 1;
    }
    poly_prep<<<64, 256>>>(filters);
    poly_mma<<<256, 128, SMEM_SZ>>>(x, out, filters, biases);
}

// round 17
// speedup vs baseline: 1.0894x; 1.0894x over previous
#include <cuda_runtime.h>
#include <cuda_fp16.h>
#include <cstdint>

// ---------------------------------------------------------------------------
// Poly2d via warp-level HMMA (mma.sync m16n8k16, fp16 in / fp32 acc).
// 54 features/channel; K packed 2x56=112 per channel pair (7 k-steps),
// 240B-stride rows (no swizzle). Round 17: bias FOLDED INTO THE GEMM —
// pad features 54/55 are constant 1.0; weight slot 54 of channel c holds
// F[o][c][0][0] (per-channel constant term, computed locally in prep),
// slot 55 of channel 0 holds biases[o]. No bias path anywhere else:
// prep is tail-free, main kernel is the exact R11 mainloop.
// 256 CTAs x 128 threads (2x2 warp grid), 2 CTAs/SM.
// ---------------------------------------------------------------------------

#define NCH   64
#define NOUT  64
#define KPAIR 112
#define ROWB  240
#define NPAIR 32

__device__ __align__(16) unsigned short g_Wp[NPAIR * NOUT * KPAIR];

// dynamic smem layout (bytes)
#define A_BUF  (64 * ROWB)                   // 15360
#define B_BUF  (NOUT * ROWB)                 // 15360
#define OFF_A  0                             // 2 x A_BUF = 30720
#define OFF_B  (2 * A_BUF)                   // 2 x B_BUF = 30720
#define OFF_X  (OFF_B + 2 * B_BUF)           // 2 x 408 floats = 3264
#define SMEM_SZ (OFF_X + 3264 + 64)

__device__ __forceinline__ uint32_t s2u(const void* p) {
    return (uint32_t)__cvta_generic_to_shared(p);
}
__device__ __forceinline__ void cpa4(uint32_t s, const void* g, bool ok) {
    asm volatile("cp.async.ca.shared.global [%0], [%1], 4, %2;\n"
                 :: "r"(s), "l"(g), "r"(ok ? 4 : 0));
}
__device__ __forceinline__ void cpa16(uint32_t s, const void* g) {
    asm volatile("cp.async.cg.shared.global [%0], [%1], 16;\n"
                 :: "r"(s), "l"(g));
}
__device__ __forceinline__ void ldsm4(uint32_t& r0, uint32_t& r1, uint32_t& r2,
                                      uint32_t& r3, uint32_t addr) {
    asm volatile("ldmatrix.sync.aligned.m8n8.x4.shared.b16 {%0,%1,%2,%3}, [%4];"
                 : "=r"(r0), "=r"(r1), "=r"(r2), "=r"(r3) : "r"(addr));
}
__device__ __forceinline__ void mma16816(float& c0, float& c1, float& c2, float& c3,
                                         uint32_t a0, uint32_t a1, uint32_t a2,
                                         uint32_t a3, uint32_t b0, uint32_t b1) {
    asm volatile(
        "mma.sync.aligned.m16n8k16.row.col.f32.f16.f16.f32 "
        "{%0,%1,%2,%3}, {%4,%5,%6,%7}, {%8,%9}, {%0,%1,%2,%3};"
        : "+f"(c0), "+f"(c1), "+f"(c2), "+f"(c3)
        : "r"(a0), "r"(a1), "r"(a2), "r"(a3), "r"(b0), "r"(b1));
}

// ---------------------------------------------------------------------------
// Prep: 64 CTAs, one channel c each; writes halves [p*56, p*56+56) (p=c&1)
// of every o-row in pair block c>>1. Feature slots:
//   k<9 linear, k in [9,54) pairs, k=54 -> F[0][0] (constant term),
//   k=55 -> biases[o] if c==0 else 0.   (A-side slots 54/55 are 1.0.)
// All 256 threads compute (o = tid&63, quarter = tid>>6). No serial tail.
// ---------------------------------------------------------------------------
__global__ void __launch_bounds__(256)
poly_prep(const float* __restrict__ filters, const float* __restrict__ biases) {
    __shared__ float fsm[NOUT * 100];                        // 25.6KB
    __shared__ __align__(16) unsigned short wsm[NOUT * 56];  // 7KB
    const int c = blockIdx.x, tid = threadIdx.x;
    const int pj = c >> 1, p = c & 1;
    const int o = tid & 63, q = tid >> 6;

    // coalesced load of filters[:, c, :, :]
    for (int i = tid; i < NOUT * 100; i += 256)
        fsm[i] = filters[(i / 100) * 6400 + c * 100 + (i % 100)];
    __syncthreads();

    {
        const float* F = fsm + o * 100;
        for (int k = 14 * q; k < 14 * q + 14; ++k) {
            float v;
            if (k < 9) {
                const int t = k + 1;
                v = F[t] + F[t * 10];
            } else if (k < 54) {
                int idx = k - 9, a = 0;
                while (idx >= 9 - a) { idx -= 9 - a; ++a; }
                const int i1 = a + 1, j1 = a + idx + 1;
                v = (i1 == j1) ? F[i1 * 10 + i1]
                               : (F[i1 * 10 + j1] + F[j1 * 10 + i1]);
            } else if (k == 54) {
                v = F[0];                       // constant term F[o][c][0][0]
            } else {
                v = (c == 0) ? biases[o] : 0.0f;  // bias added exactly once
            }
            wsm[o * 56 + k] = __half_as_ushort(__float2half_rn(v));
        }
    }
    __syncthreads();

    // store: 64 rows x 7 uint4 into g_Wp[pj][o][p*56 ..]
    const uint4* srcp = (const uint4*)wsm;
    for (int i = tid; i < 448; i += 256) {
        const int oo = i / 7, qq = i % 7;
        *(uint4*)(g_Wp + pj * NOUT * KPAIR + oo * KPAIR + p * 56 + qq * 8) =
            srcp[i];
    }
}

// ---------------------------------------------------------------------------
// Main kernel (exact R11 mainloop): 256 CTAs (b, row) x 128 threads (4 warps),
// 2x2 warp grid over D[64 px, 64 o]; iter = channel pair, K=112 (7 k-steps).
// ---------------------------------------------------------------------------
extern __shared__ unsigned char smdyn[];

__global__ void __launch_bounds__(128, 2)
poly_mma(const float* __restrict__ x, float* __restrict__ out) {
    const uint32_t smb = s2u(smdyn);
    const int tid = threadIdx.x, lane = tid & 31, wid = tid >> 5;
    const int m = tid & 63, h = tid >> 6;           // pixel col, pair-channel
    const int mrow = wid >> 1, ncol = wid & 1;      // 2x2 warp grid
    const int b = blockIdx.x >> 6;
    const int r = blockIdx.x & 63;

    float acc[2][4][4];
    #pragma unroll
    for (int mt = 0; mt < 2; ++mt)
        #pragma unroll
        for (int n8 = 0; n8 < 4; ++n8)
            #pragma unroll
            for (int q = 0; q < 4; ++q) acc[mt][n8][q] = 0.0f;

    // stage channel pair j into buffer j&1
    auto stage = [&](int j) {
        const uint32_t buf = (uint32_t)(j & 1);
        #pragma unroll
        for (int i = tid; i < 408; i += 128) {      // 2 ch x 3 rows x 68 cols
            const int p = i / 204, rem = i % 204;
            const int rr = rem / 68, col = rem % 68;
            const int gr = r - 1 + rr, gw = col - 1;
            const bool ok = ((unsigned)gr < 64u) && ((unsigned)gw < 64u);
            const int c = 2 * j + p;
            const float* src =
                x + (((b * NCH + c) * 64 + (ok ? gr : 0)) * 64 + (ok ? gw : 0));
            cpa4(smb + OFF_X + (buf * 408 + (uint32_t)i) * 4, src, ok);
        }
        const uint4* srcw = (const uint4*)(g_Wp + j * NOUT * KPAIR);
        #pragma unroll
        for (int i = tid; i < 896; i += 128) {      // 64 rows x 14 x 16B
            const int row = i / 14, col = i % 14;
            cpa16(smb + OFF_B + buf * B_BUF + (uint32_t)(row * ROWB + col * 16),
                  srcw + i);
        }
    };

    stage(0);
    asm volatile("cp.async.commit_group;" ::: "memory");

    // ldmatrix lane base offsets (no swizzle; k-step adds ks*32 bytes)
    uint32_t a_off[2], b_off[2];
    #pragma unroll
    for (int mt = 0; mt < 2; ++mt)
        a_off[mt] = (uint32_t)((mrow * 32 + mt * 16 + (lane & 15)) * ROWB +
                               (lane >> 4) * 16);
    #pragma unroll
    for (int nt = 0; nt < 2; ++nt)
        b_off[nt] = (uint32_t)((ncol * 32 + nt * 16 + (lane & 15)) * ROWB +
                               (lane >> 4) * 16);

    for (int j = 0; j < NPAIR; ++j) {
        asm volatile("cp.async.wait_group 0;" ::: "memory");
        __syncthreads();   // x[j], B[j] ready; A[j&1] free (MMA j-2 done)

        if (j + 1 < NPAIR) stage(j + 1);
        asm volatile("cp.async.commit_group;" ::: "memory");

        const uint32_t abuf = smb + OFF_A + (uint32_t)(j & 1) * A_BUF;
        const uint32_t bbuf = smb + OFF_B + (uint32_t)(j & 1) * B_BUF;

        // ---- featgen: this thread's channel (h) of the pair ----
        {
            const float* xbp =
                (const float*)(smdyn + OFF_X) + (j & 1) * 408 + h * 204;
            float t[9];
            #pragma unroll
            for (int rr = 0; rr < 3; ++rr)
                #pragma unroll
                for (int dx = 0; dx < 3; ++dx)
                    t[rr * 3 + dx] = xbp[rr * 68 + m + dx];

            float fl[54];
            #pragma unroll
            for (int tt = 0; tt < 9; ++tt) fl[tt] = t[tt];
            {
                int k = 9;
                #pragma unroll
                for (int i = 0; i < 9; ++i)
                    #pragma unroll
                    for (int jj = i; jj < 9; ++jj) fl[k++] = t[i] * t[jj];
            }

            uint32_t hr[28];
            #pragma unroll
            for (int u = 0; u < 27; ++u) {
                __half2 hh = __floats2half2_rn(fl[2 * u], fl[2 * u + 1]);
                hr[u] = *reinterpret_cast<uint32_t*>(&hh);
            }
            hr[27] = 0x3C003C00u;   // features 54,55 = (1.0h, 1.0h): bias hook

            const uint32_t dst0 = abuf + (uint32_t)(m * ROWB + h * 112);
            #pragma unroll
            for (int q = 0; q < 7; ++q)
                asm volatile("st.shared.v4.b32 [%0], {%1,%2,%3,%4};"
                             :: "r"(dst0 + (uint32_t)q * 16),
                                "r"(hr[4 * q]), "r"(hr[4 * q + 1]),
                                "r"(hr[4 * q + 2]), "r"(hr[4 * q + 3])
                             : "memory");
        }
        __syncthreads();   // A pair ready

        // ---- HMMA over K = 112 (7 k-steps) ----
        #pragma unroll
        for (int ks = 0; ks < 7; ++ks) {
            const uint32_t kl = (uint32_t)ks * 32;
            uint32_t a0[4], a1[4], bA[4], bB[4];
            ldsm4(a0[0], a0[1], a0[2], a0[3], abuf + a_off[0] + kl);
            ldsm4(a1[0], a1[1], a1[2], a1[3], abuf + a_off[1] + kl);
            ldsm4(bA[0], bA[1], bA[2], bA[3], bbuf + b_off[0] + kl);
            ldsm4(bB[0], bB[1], bB[2], bB[3], bbuf + b_off[1] + kl);

            mma16816(acc[0][0][0], acc[0][0][1], acc[0][0][2], acc[0][0][3],
                     a0[0], a0[1], a0[2], a0[3], bA[0], bA[2]);
            mma16816(acc[0][1][0], acc[0][1][1], acc[0][1][2], acc[0][1][3],
                     a0[0], a0[1], a0[2], a0[3], bA[1], bA[3]);
            mma16816(acc[0][2][0], acc[0][2][1], acc[0][2][2], acc[0][2][3],
                     a0[0], a0[1], a0[2], a0[3], bB[0], bB[2]);
            mma16816(acc[0][3][0], acc[0][3][1], acc[0][3][2], acc[0][3][3],
                     a0[0], a0[1], a0[2], a0[3], bB[1], bB[3]);
            mma16816(acc[1][0][0], acc[1][0][1], acc[1][0][2], acc[1][0][3],
                     a1[0], a1[1], a1[2], a1[3], bA[0], bA[2]);
            mma16816(acc[1][1][0], acc[1][1][1], acc[1][1][2], acc[1][1][3],
                     a1[0], a1[1], a1[2], a1[3], bA[1], bA[3]);
            mma16816(acc[1][2][0], acc[1][2][1], acc[1][2][2], acc[1][2][3],
                     a1[0], a1[1], a1[2], a1[3], bB[0], bB[2]);
            mma16816(acc[1][3][0], acc[1][3][1], acc[1][3][2], acc[1][3][3],
                     a1[0], a1[1], a1[2], a1[3], bB[1], bB[3]);
        }
    }

    // ---- epilogue: c-frag -> global (bias already in the GEMM) ----
    const int obase = ncol * 32 + (lane & 3) * 2;
    #pragma unroll
    for (int mt = 0; mt < 2; ++mt) {
        #pragma unroll
        for (int half = 0; half < 2; ++half) {
            const int cc = mrow * 32 + mt * 16 + (lane >> 2) + half * 8;
            float* op = out + ((b * NOUT) * 64 + r) * 64 + cc;
            #pragma unroll
            for (int n8 = 0; n8 < 4; ++n8) {
                const int o = obase + n8 * 8;
                op[(o)     * 4096] = acc[mt][n8][half * 2];
                op[(o + 1) * 4096] = acc[mt][n8][half * 2 + 1];
            }
        }
    }
}

// ---------------------------------------------------------------------------
extern "C" void kernel_launch(void* const* d_in, const int* in_sizes, int n_in,
                              void* d_out, int out_size) {
    const float* x       = (const float*)d_in[0];  // [4,64,64,64]
    const float* filters = (const float*)d_in[1];  // [64,64,10,10]
    const float* biases  = (const float*)d_in[2];  // [64,1]
    float* out = (float*)d_out;                    // [4,64,64,64]
    (void)in_sizes; (void)n_in; (void)out_size;

    static int attr_set = 0;
    if (!attr_set) {
        cudaFuncSetAttribute(poly_mma,
                             cudaFuncAttributeMaxDynamicSharedMemorySize,
                             SMEM_SZ);
        attr_set = 1;
    }
    poly_prep<<<64, 256>>>(filters, biases);
    poly_mma<<<256, 128, SMEM_SZ>>>(x, out);
}